// round 2
// baseline (speedup 1.0000x reference)
#include <cuda_runtime.h>
#include <math.h>

// ---------------------------------------------------------------------------
// lstm_gcn: LSTM(16 steps, N=50000, D=128) -> GCNConv -> ReLU -> GCNConv
// Round 1: fix illegal access — edges may be int32 (JAX x64 disabled) or
// int64. Device-side dtype detection + flag-branched scatter + index clamps.
// ---------------------------------------------------------------------------

#define MAXN 50000
#define DIM  128
#define NG   512   // 4*D gate columns

// scratch (device globals: no allocation allowed)
__device__ float g_h[MAXN * DIM];
__device__ float g_c[MAXN * DIM];
__device__ float g_gates[MAXN * NG];
__device__ float g_t1[MAXN * DIM];
__device__ float g_t2[MAXN * DIM];
__device__ float g_bsum[NG];
__device__ int   g_eflag;   // 1 = edges are int64, 0 = int32

// ---------------------------------------------------------------------------
// edge dtype detection: values are < 50000, so if stored as little-endian
// int64 every odd int32 word is 0. 4096 random int32 indices are never all 0.
// ---------------------------------------------------------------------------
__global__ void detect_edge_dtype_k(const int* __restrict__ e32, long long n32,
                                    int* __restrict__ flag) {
    __shared__ int nz;
    if (threadIdx.x == 0) nz = 0;
    __syncthreads();
    for (long long i = threadIdx.x; i < 4096; i += blockDim.x) {
        long long idx = 2 * i + 1;
        if (idx < n32 && e32[idx] != 0) atomicOr(&nz, 1);
    }
    __syncthreads();
    if (threadIdx.x == 0) *flag = (nz == 0) ? 1 : 0;
}

// ---------------------------------------------------------------------------
// small elementwise kernels
// ---------------------------------------------------------------------------
__global__ void fill_zero_k(float* __restrict__ p, int n) {
    int i = blockIdx.x * blockDim.x + threadIdx.x;
    if (i < n) p[i] = 0.0f;
}

__global__ void bias_sum_k(const float* __restrict__ a, const float* __restrict__ b,
                           float* __restrict__ o) {
    int i = threadIdx.x;  // launched with 512 threads
    o[i] = a[i] + b[i];
}

__global__ void fill_bias_k(float* __restrict__ out, const float* __restrict__ b, int total) {
    int i = blockIdx.x * blockDim.x + threadIdx.x;
    if (i < total) out[i] = b[i & (DIM - 1)];
}

__global__ void relu_bias_k(const float* __restrict__ in, const float* __restrict__ b,
                            float* __restrict__ out, int total) {
    int i = blockIdx.x * blockDim.x + threadIdx.x;
    if (i < total) {
        float v = in[i] + b[i & (DIM - 1)];
        out[i] = v > 0.0f ? v : 0.0f;
    }
}

// ---------------------------------------------------------------------------
// LSTM cell elementwise: gates [N,512] (i,f,g,o), updates c,h in place
// ---------------------------------------------------------------------------
__device__ __forceinline__ float sigf(float x) {
    return 0.5f * (1.0f + tanhf(0.5f * x));
}

__global__ void lstm_cell_k(const float* __restrict__ gates,
                            float* __restrict__ c, float* __restrict__ h, int Nn) {
    int idx = blockIdx.x * blockDim.x + threadIdx.x;
    if (idx >= Nn * 32) return;
    int n = idx >> 5;
    int q = (idx & 31) * 4;
    const float* gr = gates + (size_t)n * NG + q;
    float4 gi = *(const float4*)(gr);
    float4 gf = *(const float4*)(gr + 128);
    float4 gg = *(const float4*)(gr + 256);
    float4 go = *(const float4*)(gr + 384);
    float* cp = c + (size_t)n * DIM + q;
    float* hp = h + (size_t)n * DIM + q;
    float4 cv = *(const float4*)cp;
    float4 cn, hn;
    cn.x = sigf(gf.x) * cv.x + sigf(gi.x) * tanhf(gg.x);
    cn.y = sigf(gf.y) * cv.y + sigf(gi.y) * tanhf(gg.y);
    cn.z = sigf(gf.z) * cv.z + sigf(gi.z) * tanhf(gg.z);
    cn.w = sigf(gf.w) * cv.w + sigf(gi.w) * tanhf(gg.w);
    hn.x = sigf(go.x) * tanhf(cn.x);
    hn.y = sigf(go.y) * tanhf(cn.y);
    hn.z = sigf(go.z) * tanhf(cn.z);
    hn.w = sigf(go.w) * tanhf(cn.w);
    *(float4*)cp = cn;
    *(float4*)hp = hn;
}

// ---------------------------------------------------------------------------
// SGEMM common tiling: 128x128 block tile, BK=16, 256 threads, 8x8 microtile
// ---------------------------------------------------------------------------
#define BM 128
#define BN 128
#define BK 16
#define TM 8
#define TN 8

// LSTM gates GEMM: C[m, n] = sum_{k<128} A0[m,k]*B0[n,k]
//                          + sum_{k<128} A1[m,k]*B1[n,k] + bias[n]
__global__ __launch_bounds__(256) void gemm_lstm_k(
    const float* __restrict__ A0, const float* __restrict__ A1,
    const float* __restrict__ B0, const float* __restrict__ B1,
    const float* __restrict__ bias,
    float* __restrict__ C, int M) {
    __shared__ float As[BK][BM];
    __shared__ float Bs[BK][BN];
    int tid = threadIdx.x;
    int m0 = blockIdx.x * BM;
    int n0 = blockIdx.y * BN;
    int ty = tid >> 4;
    int tx = tid & 15;
    float acc[TM][TN] = {};

    for (int kc = 0; kc < 16; ++kc) {          // K=256, 16 chunks of 16
        int kbase = kc * BK;
        const float* Ap = (kbase < 128) ? A0 : A1;
        const float* Bp = (kbase < 128) ? B0 : B1;
        int kk = kbase & 127;
#pragma unroll
        for (int p = 0; p < 2; ++p) {          // A tile (transposed into smem)
            int ar = (tid >> 2) + p * 64;
            int ac = (tid & 3) * 4;
            int gm = m0 + ar;
            float4 v = make_float4(0.f, 0.f, 0.f, 0.f);
            if (gm < M) v = *(const float4*)(Ap + (size_t)gm * DIM + kk + ac);
            As[ac + 0][ar] = v.x; As[ac + 1][ar] = v.y;
            As[ac + 2][ar] = v.z; As[ac + 3][ar] = v.w;
        }
#pragma unroll
        for (int p = 0; p < 2; ++p) {          // B tile ([N,K] k-major -> transpose)
            int br = (tid >> 2) + p * 64;
            int bc = (tid & 3) * 4;
            float4 v = *(const float4*)(Bp + (size_t)(n0 + br) * DIM + kk + bc);
            Bs[bc + 0][br] = v.x; Bs[bc + 1][br] = v.y;
            Bs[bc + 2][br] = v.z; Bs[bc + 3][br] = v.w;
        }
        __syncthreads();
#pragma unroll
        for (int k = 0; k < BK; ++k) {
            float a[TM], b[TN];
            *(float4*)&a[0] = *(const float4*)&As[k][ty * TM];
            *(float4*)&a[4] = *(const float4*)&As[k][ty * TM + 4];
            *(float4*)&b[0] = *(const float4*)&Bs[k][tx * TN];
            *(float4*)&b[4] = *(const float4*)&Bs[k][tx * TN + 4];
#pragma unroll
            for (int i = 0; i < TM; ++i)
#pragma unroll
                for (int j = 0; j < TN; ++j) acc[i][j] += a[i] * b[j];
        }
        __syncthreads();
    }

#pragma unroll
    for (int i = 0; i < TM; ++i) {
        int m = m0 + ty * TM + i;
        if (m >= M) continue;
        float* crow = C + (size_t)m * NG + n0 + tx * TN;
        const float* brow = bias + n0 + tx * TN;
#pragma unroll
        for (int j4 = 0; j4 < TN; j4 += 4) {
            float4 o;
            o.x = acc[i][j4 + 0] + brow[j4 + 0];
            o.y = acc[i][j4 + 1] + brow[j4 + 1];
            o.z = acc[i][j4 + 2] + brow[j4 + 2];
            o.w = acc[i][j4 + 3] + brow[j4 + 3];
            *(float4*)(crow + j4) = o;
        }
    }
}

// GCN GEMM: C[M,128] = A[M,128] @ B[128,128], B stored [K,N] row-major
__global__ __launch_bounds__(256) void gemm_kn_k(
    const float* __restrict__ A, const float* __restrict__ B,
    float* __restrict__ C, int M) {
    __shared__ float As[BK][BM];
    __shared__ float Bs[BK][BN];
    int tid = threadIdx.x;
    int m0 = blockIdx.x * BM;
    int ty = tid >> 4;
    int tx = tid & 15;
    float acc[TM][TN] = {};

    for (int kc = 0; kc < 8; ++kc) {           // K=128, 8 chunks of 16
        int kbase = kc * BK;
#pragma unroll
        for (int p = 0; p < 2; ++p) {          // A tile (transpose)
            int ar = (tid >> 2) + p * 64;
            int ac = (tid & 3) * 4;
            int gm = m0 + ar;
            float4 v = make_float4(0.f, 0.f, 0.f, 0.f);
            if (gm < M) v = *(const float4*)(A + (size_t)gm * DIM + kbase + ac);
            As[ac + 0][ar] = v.x; As[ac + 1][ar] = v.y;
            As[ac + 2][ar] = v.z; As[ac + 3][ar] = v.w;
        }
#pragma unroll
        for (int p = 0; p < 2; ++p) {          // B tile ([K,N]: direct copy)
            int k = (tid >> 5) + p * 8;
            int c4 = (tid & 31) * 4;
            float4 v = *(const float4*)(B + (size_t)(kbase + k) * DIM + c4);
            *(float4*)&Bs[k][c4] = v;
        }
        __syncthreads();
#pragma unroll
        for (int k = 0; k < BK; ++k) {
            float a[TM], b[TN];
            *(float4*)&a[0] = *(const float4*)&As[k][ty * TM];
            *(float4*)&a[4] = *(const float4*)&As[k][ty * TM + 4];
            *(float4*)&b[0] = *(const float4*)&Bs[k][tx * TN];
            *(float4*)&b[4] = *(const float4*)&Bs[k][tx * TN + 4];
#pragma unroll
            for (int i = 0; i < TM; ++i)
#pragma unroll
                for (int j = 0; j < TN; ++j) acc[i][j] += a[i] * b[j];
        }
        __syncthreads();
    }

#pragma unroll
    for (int i = 0; i < TM; ++i) {
        int m = m0 + ty * TM + i;
        if (m >= M) continue;
        float* crow = C + (size_t)m * DIM + tx * TN;
#pragma unroll
        for (int j4 = 0; j4 < TN; j4 += 4) {
            float4 o;
            o.x = acc[i][j4 + 0]; o.y = acc[i][j4 + 1];
            o.z = acc[i][j4 + 2]; o.w = acc[i][j4 + 3];
            *(float4*)(crow + j4) = o;
        }
    }
}

// ---------------------------------------------------------------------------
// GCN scatter: one warp per edge, lane = float4 feature chunk.
// out[dst] += feat[src] (atomic). Edge dtype selected by device flag.
// ---------------------------------------------------------------------------
__global__ void scatter_add_k(const float* __restrict__ feat,
                              const void* __restrict__ edges_raw, long long E,
                              const int* __restrict__ eflag, int Nn,
                              float* __restrict__ out) {
    long long gt = (long long)blockIdx.x * blockDim.x + threadIdx.x;
    long long e = gt >> 5;
    if (e >= E) return;
    int lane = (int)(gt & 31);
    long long s, d;
    if (*eflag) {
        const long long* ed = (const long long*)edges_raw;
        s = ed[e];
        d = ed[E + e];
    } else {
        const int* ed = (const int*)edges_raw;
        s = ed[e];
        d = ed[E + e];
    }
    if (s < 0 || s >= Nn || d < 0 || d >= Nn) return;  // safety clamp
    float4 v = *(const float4*)(feat + s * DIM + lane * 4);
    float* o = out + d * DIM + lane * 4;
    atomicAdd(o + 0, v.x);
    atomicAdd(o + 1, v.y);
    atomicAdd(o + 2, v.z);
    atomicAdd(o + 3, v.w);
}

// ---------------------------------------------------------------------------
// host launcher
// ---------------------------------------------------------------------------
extern "C" void kernel_launch(void* const* d_in, const int* in_sizes, int n_in,
                              void* d_out, int out_size) {
    const float* input_aux = (const float*)d_in[0];
    const void*  edges     = d_in[1];
    const float* W_ih      = (const float*)d_in[2];
    const float* W_hh      = (const float*)d_in[3];
    const float* b_ih      = (const float*)d_in[4];
    const float* b_hh      = (const float*)d_in[5];
    const float* W1        = (const float*)d_in[6];
    const float* b1        = (const float*)d_in[7];
    const float* W2        = (const float*)d_in[8];
    const float* b2        = (const float*)d_in[9];
    float* out = (float*)d_out;

    int Nn  = out_size / DIM;                 // 50000
    int seq = in_sizes[0] / (Nn * DIM);       // 16
    long long E = (long long)in_sizes[1] / 2; // 1.6M edges

    float *h, *c, *gates, *t1, *t2, *bsum;
    int* eflag;
    cudaGetSymbolAddress((void**)&h,     g_h);
    cudaGetSymbolAddress((void**)&c,     g_c);
    cudaGetSymbolAddress((void**)&gates, g_gates);
    cudaGetSymbolAddress((void**)&t1,    g_t1);
    cudaGetSymbolAddress((void**)&t2,    g_t2);
    cudaGetSymbolAddress((void**)&bsum,  g_bsum);
    cudaGetSymbolAddress((void**)&eflag, g_eflag);

    int nd = Nn * DIM;
    int eb = 256;

    detect_edge_dtype_k<<<1, 256>>>((const int*)edges, 2 * E, eflag);
    bias_sum_k<<<1, NG>>>(b_ih, b_hh, bsum);
    fill_zero_k<<<(nd + eb - 1) / eb, eb>>>(h, nd);
    fill_zero_k<<<(nd + eb - 1) / eb, eb>>>(c, nd);

    dim3 ggate((Nn + BM - 1) / BM, NG / BN);  // 391 x 4
    int cell_threads = Nn * 32;
    for (int t = 0; t < seq; ++t) {
        const float* xt = input_aux + (size_t)t * Nn * DIM;
        gemm_lstm_k<<<ggate, 256>>>(xt, h, W_ih, W_hh, bsum, gates, Nn);
        lstm_cell_k<<<(cell_threads + eb - 1) / eb, eb>>>(gates, c, h, Nn);
    }

    dim3 ggcn((Nn + BM - 1) / BM, 1);
    long long sth = E * 32;
    unsigned sblocks = (unsigned)((sth + eb - 1) / eb);

    // GCN layer 1: t1 = h @ W1 ; t2 = scatter(t1) ; t1 = relu(t2 + b1)
    gemm_kn_k<<<ggcn, 256>>>(h, W1, t1, Nn);
    fill_zero_k<<<(nd + eb - 1) / eb, eb>>>(t2, nd);
    scatter_add_k<<<sblocks, eb>>>(t1, edges, E, eflag, Nn, t2);
    relu_bias_k<<<(nd + eb - 1) / eb, eb>>>(t2, b1, t1, nd);

    // GCN layer 2: t2 = t1 @ W2 ; out = b2 + scatter(t2)
    gemm_kn_k<<<ggcn, 256>>>(t1, W2, t2, Nn);
    fill_bias_k<<<(nd + eb - 1) / eb, eb>>>(out, b2, nd);
    scatter_add_k<<<sblocks, eb>>>(t2, edges, E, eflag, Nn, out);
}

// round 4
// speedup vs baseline: 1.7609x; 1.7609x over previous
#include <cuda_runtime.h>
#include <cuda_bf16.h>
#include <math.h>
#include <stdint.h>

// ---------------------------------------------------------------------------
// lstm_gcn round 4: warp-level bf16 mma.sync LSTM gate GEMM (tcgen05 is not
// available: harness PTX target is plain compute_103, 'a'-features rejected).
// gates = [x_t | h] @ [W_ih ; W_hh]^T + b via 3-pass split-bf16, fp32 acc.
// ---------------------------------------------------------------------------

#define MAXN   50000
#define MAXSEQ 16
#define DIM    128
#define NG     512

__device__ float g_h[MAXN * DIM];
__device__ float g_c[MAXN * DIM];
__device__ float g_gates[MAXN * NG];
__device__ float g_t1[MAXN * DIM];
__device__ float g_t2[MAXN * DIM];
__device__ float g_bsum[NG];
__device__ int   g_eflag;

__device__ __nv_bfloat16 g_xhi[MAXSEQ * MAXN * DIM];
__device__ __nv_bfloat16 g_xlo[MAXSEQ * MAXN * DIM];
__device__ __nv_bfloat16 g_hhi[MAXN * DIM];
__device__ __nv_bfloat16 g_hlo[MAXN * DIM];
__device__ __nv_bfloat16 g_wchi[NG * 256];   // [512][256] = [W_ih | W_hh] hi
__device__ __nv_bfloat16 g_wclo[NG * 256];   // lo

// ------------------------------ helpers ------------------------------------
__device__ __forceinline__ uint32_t smem_u32(const void* p) {
    uint32_t a;
    asm("{ .reg .u64 t; cvta.to.shared.u64 t, %1; cvt.u32.u64 %0, t; }"
        : "=r"(a) : "l"(p));
    return a;
}

__device__ __forceinline__ void ldsm4(uint32_t* r, uint32_t addr) {
    asm volatile("ldmatrix.sync.aligned.m8n8.x4.shared.b16 {%0,%1,%2,%3}, [%4];"
                 : "=r"(r[0]), "=r"(r[1]), "=r"(r[2]), "=r"(r[3]) : "r"(addr));
}

__device__ __forceinline__ void mma_bf16(float* d, const uint32_t* a,
                                         const uint32_t* b) {
    asm volatile(
        "mma.sync.aligned.m16n8k16.row.col.f32.bf16.bf16.f32 "
        "{%0,%1,%2,%3}, {%4,%5,%6,%7}, {%8,%9}, {%0,%1,%2,%3};"
        : "+f"(d[0]), "+f"(d[1]), "+f"(d[2]), "+f"(d[3])
        : "r"(a[0]), "r"(a[1]), "r"(a[2]), "r"(a[3]), "r"(b[0]), "r"(b[1]));
}

__device__ __forceinline__ void cp_async16(uint32_t dst, const void* src) {
    asm volatile("cp.async.cg.shared.global [%0], [%1], 16;"
                 :: "r"(dst), "l"(src));
}
__device__ __forceinline__ void cp_commit() {
    asm volatile("cp.async.commit_group;");
}
__device__ __forceinline__ void cp_wait1() {
    asm volatile("cp.async.wait_group 1;");
}
__device__ __forceinline__ void cp_wait0() {
    asm volatile("cp.async.wait_group 0;");
}

// ------------------------------ edge dtype detect --------------------------
__global__ void detect_edge_dtype_k(const int* __restrict__ e32, long long n32,
                                    int* __restrict__ flag) {
    __shared__ int nz;
    if (threadIdx.x == 0) nz = 0;
    __syncthreads();
    for (long long i = threadIdx.x; i < 4096; i += blockDim.x) {
        long long idx = 2 * i + 1;
        if (idx < n32 && e32[idx] != 0) atomicOr(&nz, 1);
    }
    __syncthreads();
    if (threadIdx.x == 0) *flag = (nz == 0) ? 1 : 0;
}

// ------------------------------ small kernels ------------------------------
__global__ void fill_zero_k(float* __restrict__ p, int n) {
    int i = blockIdx.x * blockDim.x + threadIdx.x;
    if (i < n) p[i] = 0.0f;
}

__global__ void bias_sum_k(const float* __restrict__ a, const float* __restrict__ b,
                           float* __restrict__ o) {
    int i = threadIdx.x;
    o[i] = a[i] + b[i];
}

__global__ void fill_bias_k(float* __restrict__ out, const float* __restrict__ b, int total) {
    int i = blockIdx.x * blockDim.x + threadIdx.x;
    if (i < total) out[i] = b[i & (DIM - 1)];
}

__global__ void relu_bias_k(const float* __restrict__ in, const float* __restrict__ b,
                            float* __restrict__ out, int total) {
    int i = blockIdx.x * blockDim.x + threadIdx.x;
    if (i < total) {
        float v = in[i] + b[i & (DIM - 1)];
        out[i] = v > 0.0f ? v : 0.0f;
    }
}

__global__ void split_bf16_k(const float* __restrict__ src,
                             __nv_bfloat16* __restrict__ hi,
                             __nv_bfloat16* __restrict__ lo, int n4) {
    int i = blockIdx.x * blockDim.x + threadIdx.x;
    if (i >= n4) return;
    float4 v = ((const float4*)src)[i];
    __nv_bfloat16 hx = __float2bfloat16(v.x), hy = __float2bfloat16(v.y);
    __nv_bfloat16 hz = __float2bfloat16(v.z), hw = __float2bfloat16(v.w);
    __nv_bfloat162* hp = (__nv_bfloat162*)(hi + (size_t)i * 4);
    __nv_bfloat162* lp = (__nv_bfloat162*)(lo + (size_t)i * 4);
    hp[0] = __nv_bfloat162(hx, hy);
    hp[1] = __nv_bfloat162(hz, hw);
    lp[0] = __nv_bfloat162(__float2bfloat16(v.x - __bfloat162float(hx)),
                           __float2bfloat16(v.y - __bfloat162float(hy)));
    lp[1] = __nv_bfloat162(__float2bfloat16(v.z - __bfloat162float(hz)),
                           __float2bfloat16(v.w - __bfloat162float(hw)));
}

__global__ void build_wcat_k(const float* __restrict__ wih, const float* __restrict__ whh,
                             __nv_bfloat16* __restrict__ hi, __nv_bfloat16* __restrict__ lo) {
    int idx = blockIdx.x * blockDim.x + threadIdx.x;
    if (idx >= NG * 256) return;
    int n = idx >> 8, k = idx & 255;
    float v = (k < 128) ? wih[n * 128 + k] : whh[n * 128 + (k - 128)];
    __nv_bfloat16 h = __float2bfloat16(v);
    hi[idx] = h;
    lo[idx] = __float2bfloat16(v - __bfloat162float(h));
}

// ------------------------------ LSTM cell ----------------------------------
__device__ __forceinline__ float sigf(float x) {
    return 0.5f * (1.0f + tanhf(0.5f * x));
}

__global__ void lstm_cell_k(const float* __restrict__ gates,
                            float* __restrict__ c, float* __restrict__ h,
                            __nv_bfloat16* __restrict__ hhi,
                            __nv_bfloat16* __restrict__ hlo, int Nn) {
    int idx = blockIdx.x * blockDim.x + threadIdx.x;
    if (idx >= Nn * 32) return;
    int n = idx >> 5;
    int q = (idx & 31) * 4;
    const float* gr = gates + (size_t)n * NG + q;
    float4 gi = *(const float4*)(gr);
    float4 gf = *(const float4*)(gr + 128);
    float4 gg = *(const float4*)(gr + 256);
    float4 go = *(const float4*)(gr + 384);
    float* cp = c + (size_t)n * DIM + q;
    float* hp = h + (size_t)n * DIM + q;
    float4 cv = *(const float4*)cp;
    float4 cn, hn;
    cn.x = sigf(gf.x) * cv.x + sigf(gi.x) * tanhf(gg.x);
    cn.y = sigf(gf.y) * cv.y + sigf(gi.y) * tanhf(gg.y);
    cn.z = sigf(gf.z) * cv.z + sigf(gi.z) * tanhf(gg.z);
    cn.w = sigf(gf.w) * cv.w + sigf(gi.w) * tanhf(gg.w);
    hn.x = sigf(go.x) * tanhf(cn.x);
    hn.y = sigf(go.y) * tanhf(cn.y);
    hn.z = sigf(go.z) * tanhf(cn.z);
    hn.w = sigf(go.w) * tanhf(cn.w);
    *(float4*)cp = cn;
    *(float4*)hp = hn;
    __nv_bfloat16 hx = __float2bfloat16(hn.x), hy = __float2bfloat16(hn.y);
    __nv_bfloat16 hz = __float2bfloat16(hn.z), hw = __float2bfloat16(hn.w);
    __nv_bfloat162* hip = (__nv_bfloat162*)(hhi + (size_t)n * DIM + q);
    __nv_bfloat162* lop = (__nv_bfloat162*)(hlo + (size_t)n * DIM + q);
    hip[0] = __nv_bfloat162(hx, hy);
    hip[1] = __nv_bfloat162(hz, hw);
    lop[0] = __nv_bfloat162(__float2bfloat16(hn.x - __bfloat162float(hx)),
                            __float2bfloat16(hn.y - __bfloat162float(hy)));
    lop[1] = __nv_bfloat162(__float2bfloat16(hn.z - __bfloat162float(hz)),
                            __float2bfloat16(hn.w - __bfloat162float(hw)));
}

// ---------------------------------------------------------------------------
// LSTM gate GEMM via mma.sync bf16.
// Block tile 128x128, 8 warps (2x4) of 64x32 warp tiles, BK=32, double-
// buffered cp.async. K loop: 3 passes x 256 (x | h), 24 iterations.
// smem rows padded to 80B (conflict-free ldmatrix: banks 20r+4c mod 32).
// ---------------------------------------------------------------------------
#define ROWB 80     // bytes per smem row (32 bf16 data + pad)
#define ATILE 10240 // 128 * 80
#define NITER 24

__global__ __launch_bounds__(256, 2) void gemm_lstm_mma(
    const __nv_bfloat16* __restrict__ xhi, const __nv_bfloat16* __restrict__ xlo,
    const __nv_bfloat16* __restrict__ hhi, const __nv_bfloat16* __restrict__ hlo,
    const __nv_bfloat16* __restrict__ whi, const __nv_bfloat16* __restrict__ wlo,
    const float* __restrict__ bias,
    float* __restrict__ C, int M) {
    __shared__ __align__(128) char sm[4 * ATILE];  // A0 A1 B0 B1

    int tid  = threadIdx.x;
    int wid  = tid >> 5;
    int lane = tid & 31;
    int m0 = blockIdx.x * 128;
    int n0 = blockIdx.y * 128;

    uint32_t sbase = smem_u32(sm);
    // warp tile position: 2 rows x 4 cols
    int wm = (wid >> 2) * 64;
    int wn = (wid & 3) * 32;

    // ldmatrix per-lane addressing offsets
    int a_row  = (lane & 7) + ((lane >> 3) & 1) * 8;  // within m16
    int a_kch  = lane >> 4;                            // 0/1 -> k half chunk
    int b_row  = (lane & 7) + (lane >> 4) * 8;         // within n16
    int b_kch  = (lane >> 3) & 1;

    // cp.async per-thread src/dst (2 chunks for A, 2 for B)
    int r0c = tid >> 2;             // rows 0..63   (chunk tid&3)
    int ch  = (tid & 3);

    float acc[4][4][4];
#pragma unroll
    for (int i = 0; i < 4; ++i)
#pragma unroll
        for (int j = 0; j < 4; ++j)
#pragma unroll
            for (int q = 0; q < 4; ++q) acc[i][j][q] = 0.0f;

    // ---- load issue for iteration i into buffer b ----
    auto issue = [&](int i, int b) {
        int pass = i >> 3;          // 0,1,2
        int kc   = i & 7;           // 0..7 over K=256
        bool xp  = kc < 4;
        const __nv_bfloat16* Ap = (pass == 2) ? (xp ? xlo : hlo)
                                              : (xp ? xhi : hhi);
        const __nv_bfloat16* Bp = (pass == 1) ? wlo : whi;
        int ka = (kc & 3) * 32;     // col in 128-wide x/h
        int kb = kc * 32;           // col in 256-wide Wcat

        uint32_t dA = sbase + b * ATILE;
        uint32_t dB = sbase + 2 * ATILE + b * ATILE;
#pragma unroll
        for (int it = 0; it < 2; ++it) {
            int r = r0c + it * 64;
            int gm = m0 + r;
            const __nv_bfloat16* src =
                Ap + (size_t)(gm < M ? gm : 0) * DIM + ka + ch * 8;
            cp_async16(dA + r * ROWB + ch * 16, src);
        }
#pragma unroll
        for (int it = 0; it < 2; ++it) {
            int r = r0c + it * 64;
            const __nv_bfloat16* src = Bp + (size_t)(n0 + r) * 256 + kb + ch * 8;
            cp_async16(dB + r * ROWB + ch * 16, src);
        }
        cp_commit();
    };

    issue(0, 0);

    for (int i = 0; i < NITER; ++i) {
        if (i + 1 < NITER) issue(i + 1, (i + 1) & 1);
        if (i + 1 < NITER) cp_wait1(); else cp_wait0();
        __syncthreads();

        int b = i & 1;
        uint32_t sA = sbase + b * ATILE;
        uint32_t sB = sbase + 2 * ATILE + b * ATILE;

#pragma unroll
        for (int k16 = 0; k16 < 2; ++k16) {
            uint32_t afr[4][4];
            uint32_t bfr[2][4];
#pragma unroll
            for (int fm = 0; fm < 4; ++fm) {
                uint32_t addr = sA + (wm + fm * 16 + a_row) * ROWB
                              + (k16 * 2 + a_kch) * 16;
                ldsm4(afr[fm], addr);
            }
#pragma unroll
            for (int fn2 = 0; fn2 < 2; ++fn2) {
                uint32_t addr = sB + (wn + fn2 * 16 + b_row) * ROWB
                              + (k16 * 2 + b_kch) * 16;
                ldsm4(bfr[fn2], addr);
            }
#pragma unroll
            for (int fm = 0; fm < 4; ++fm) {
#pragma unroll
                for (int fn = 0; fn < 4; ++fn)
                    mma_bf16(acc[fm][fn], afr[fm], &bfr[fn >> 1][(fn & 1) * 2]);
            }
        }
        __syncthreads();
    }

    // ---- epilogue: add bias, store fp32 gates ----
    int gid = lane >> 2;
    int tig = lane & 3;
    float2 bfr2[4];
#pragma unroll
    for (int fn = 0; fn < 4; ++fn) {
        int n = n0 + wn + fn * 8 + tig * 2;
        bfr2[fn] = *(const float2*)(bias + n);
    }
#pragma unroll
    for (int fm = 0; fm < 4; ++fm) {
        int mlo = m0 + wm + fm * 16 + gid;
        int mhi = mlo + 8;
#pragma unroll
        for (int fn = 0; fn < 4; ++fn) {
            int n = n0 + wn + fn * 8 + tig * 2;
            if (mlo < M) {
                float2 o = make_float2(acc[fm][fn][0] + bfr2[fn].x,
                                       acc[fm][fn][1] + bfr2[fn].y);
                *(float2*)(C + (size_t)mlo * NG + n) = o;
            }
            if (mhi < M) {
                float2 o = make_float2(acc[fm][fn][2] + bfr2[fn].x,
                                       acc[fm][fn][3] + bfr2[fn].y);
                *(float2*)(C + (size_t)mhi * NG + n) = o;
            }
        }
    }
}

// ------------------------------ GCN fp32 GEMM ------------------------------
#define BM 128
#define BN 128
#define BK 16
#define TM 8
#define TN 8

__global__ __launch_bounds__(256) void gemm_kn_k(
    const float* __restrict__ A, const float* __restrict__ B,
    float* __restrict__ C, int M) {
    __shared__ float As[BK][BM];
    __shared__ float Bs[BK][BN];
    int tid = threadIdx.x;
    int m0 = blockIdx.x * BM;
    int ty = tid >> 4;
    int tx = tid & 15;
    float acc[TM][TN] = {};

    for (int kc = 0; kc < 8; ++kc) {
        int kbase = kc * BK;
#pragma unroll
        for (int p = 0; p < 2; ++p) {
            int ar = (tid >> 2) + p * 64;
            int ac = (tid & 3) * 4;
            int gm = m0 + ar;
            float4 v = make_float4(0.f, 0.f, 0.f, 0.f);
            if (gm < M) v = *(const float4*)(A + (size_t)gm * DIM + kbase + ac);
            As[ac + 0][ar] = v.x; As[ac + 1][ar] = v.y;
            As[ac + 2][ar] = v.z; As[ac + 3][ar] = v.w;
        }
#pragma unroll
        for (int p = 0; p < 2; ++p) {
            int k = (tid >> 5) + p * 8;
            int c4 = (tid & 31) * 4;
            float4 v = *(const float4*)(B + (size_t)(kbase + k) * DIM + c4);
            *(float4*)&Bs[k][c4] = v;
        }
        __syncthreads();
#pragma unroll
        for (int k = 0; k < BK; ++k) {
            float a[TM], b[TN];
            *(float4*)&a[0] = *(const float4*)&As[k][ty * TM];
            *(float4*)&a[4] = *(const float4*)&As[k][ty * TM + 4];
            *(float4*)&b[0] = *(const float4*)&Bs[k][tx * TN];
            *(float4*)&b[4] = *(const float4*)&Bs[k][tx * TN + 4];
#pragma unroll
            for (int i = 0; i < TM; ++i)
#pragma unroll
                for (int j = 0; j < TN; ++j) acc[i][j] += a[i] * b[j];
        }
        __syncthreads();
    }

#pragma unroll
    for (int i = 0; i < TM; ++i) {
        int m = m0 + ty * TM + i;
        if (m >= M) continue;
        float* crow = C + (size_t)m * DIM + tx * TN;
#pragma unroll
        for (int j4 = 0; j4 < TN; j4 += 4) {
            float4 o;
            o.x = acc[i][j4 + 0]; o.y = acc[i][j4 + 1];
            o.z = acc[i][j4 + 2]; o.w = acc[i][j4 + 3];
            *(float4*)(crow + j4) = o;
        }
    }
}

// ------------------------------ GCN scatter --------------------------------
__global__ void scatter_add_k(const float* __restrict__ feat,
                              const void* __restrict__ edges_raw, long long E,
                              const int* __restrict__ eflag, int Nn,
                              float* __restrict__ out) {
    long long gt = (long long)blockIdx.x * blockDim.x + threadIdx.x;
    long long e = gt >> 5;
    if (e >= E) return;
    int lane = (int)(gt & 31);
    long long s, d;
    if (*eflag) {
        const long long* ed = (const long long*)edges_raw;
        s = ed[e];
        d = ed[E + e];
    } else {
        const int* ed = (const int*)edges_raw;
        s = ed[e];
        d = ed[E + e];
    }
    if (s < 0 || s >= Nn || d < 0 || d >= Nn) return;
    float4 v = *(const float4*)(feat + s * DIM + lane * 4);
    float* o = out + d * DIM + lane * 4;
    atomicAdd(o + 0, v.x);
    atomicAdd(o + 1, v.y);
    atomicAdd(o + 2, v.z);
    atomicAdd(o + 3, v.w);
}

// ------------------------------ host launcher ------------------------------
extern "C" void kernel_launch(void* const* d_in, const int* in_sizes, int n_in,
                              void* d_out, int out_size) {
    const float* input_aux = (const float*)d_in[0];
    const void*  edges     = d_in[1];
    const float* W_ih      = (const float*)d_in[2];
    const float* W_hh      = (const float*)d_in[3];
    const float* b_ih      = (const float*)d_in[4];
    const float* b_hh      = (const float*)d_in[5];
    const float* W1        = (const float*)d_in[6];
    const float* b1        = (const float*)d_in[7];
    const float* W2        = (const float*)d_in[8];
    const float* b2        = (const float*)d_in[9];
    float* out = (float*)d_out;

    int Nn  = out_size / DIM;
    int seq = in_sizes[0] / (Nn * DIM);
    long long E = (long long)in_sizes[1] / 2;

    float *h, *c, *gates, *t1, *t2, *bsum;
    int* eflag;
    __nv_bfloat16 *xhi, *xlo, *hhi, *hlo, *wchi, *wclo;
    cudaGetSymbolAddress((void**)&h,     g_h);
    cudaGetSymbolAddress((void**)&c,     g_c);
    cudaGetSymbolAddress((void**)&gates, g_gates);
    cudaGetSymbolAddress((void**)&t1,    g_t1);
    cudaGetSymbolAddress((void**)&t2,    g_t2);
    cudaGetSymbolAddress((void**)&bsum,  g_bsum);
    cudaGetSymbolAddress((void**)&eflag, g_eflag);
    cudaGetSymbolAddress((void**)&xhi,   g_xhi);
    cudaGetSymbolAddress((void**)&xlo,   g_xlo);
    cudaGetSymbolAddress((void**)&hhi,   g_hhi);
    cudaGetSymbolAddress((void**)&hlo,   g_hlo);
    cudaGetSymbolAddress((void**)&wchi,  g_wchi);
    cudaGetSymbolAddress((void**)&wclo,  g_wclo);

    int nd = Nn * DIM;
    int eb = 256;

    detect_edge_dtype_k<<<1, 256>>>((const int*)edges, 2 * E, eflag);
    bias_sum_k<<<1, NG>>>(b_ih, b_hh, bsum);
    fill_zero_k<<<(nd + eb - 1) / eb, eb>>>(h, nd);
    fill_zero_k<<<(nd + eb - 1) / eb, eb>>>(c, nd);
    fill_zero_k<<<(nd / 2 + eb - 1) / eb, eb>>>((float*)hhi, nd / 2);
    fill_zero_k<<<(nd / 2 + eb - 1) / eb, eb>>>((float*)hlo, nd / 2);

    int xn4 = (seq * nd) / 4;
    split_bf16_k<<<(xn4 + eb - 1) / eb, eb>>>(input_aux, xhi, xlo, xn4);
    build_wcat_k<<<(NG * 256 + eb - 1) / eb, eb>>>(W_ih, W_hh, wchi, wclo);

    dim3 ggate((Nn + 127) / 128, 4);
    int cell_threads = Nn * 32;
    for (int t = 0; t < seq; ++t) {
        const __nv_bfloat16* xh = xhi + (size_t)t * nd;
        const __nv_bfloat16* xl = xlo + (size_t)t * nd;
        gemm_lstm_mma<<<ggate, 256>>>(xh, xl, hhi, hlo, wchi, wclo,
                                      bsum, gates, Nn);
        lstm_cell_k<<<(cell_threads + eb - 1) / eb, eb>>>(gates, c, h, hhi, hlo, Nn);
    }

    dim3 ggcn((Nn + BM - 1) / BM, 1);
    long long sth = E * 32;
    unsigned sblocks = (unsigned)((sth + eb - 1) / eb);

    gemm_kn_k<<<ggcn, 256>>>(h, W1, t1, Nn);
    fill_zero_k<<<(nd + eb - 1) / eb, eb>>>(t2, nd);
    scatter_add_k<<<sblocks, eb>>>(t1, edges, E, eflag, Nn, t2);
    relu_bias_k<<<(nd + eb - 1) / eb, eb>>>(t2, b1, t1, nd);

    gemm_kn_k<<<ggcn, 256>>>(t1, W2, t2, Nn);
    fill_bias_k<<<(nd + eb - 1) / eb, eb>>>(out, b2, nd);
    scatter_add_k<<<sblocks, eb>>>(t2, edges, E, eflag, Nn, out);
}